// round 1
// baseline (speedup 1.0000x reference)
#include <cuda_runtime.h>

// Problem constants
constexpr int B  = 4;
constexpr int T  = 4096;
constexpr int C  = 512;
constexpr int HS = 64;
constexpr int TR = T / 64;                 // 64 query row-tiles per batch
constexpr float LOG2E = 1.4426950408889634f;
constexpr int FLASH_SMEM = 4 * 64 * 65 * (int)sizeof(float);   // Qs,Ks,Vs,Ps

// Scratch for projected q,k,v (4 MB each) — __device__ globals, no allocation.
__device__ float g_q[B * T * HS];
__device__ float g_k[B * T * HS];
__device__ float g_v[B * T * HS];

// ---------------------------------------------------------------------------
// Projection: dst[M,64] = x[M,512] @ W[512,64], for W in {Wq, Wk, Wv}.
// grid = (M/64, 3), block = 256.  Thread (ty,tx): rows ty+16i, cols 4*tx+j.
// ---------------------------------------------------------------------------
__global__ __launch_bounds__(256) void proj_kernel(
    const float* __restrict__ x,
    const float* __restrict__ Wk,
    const float* __restrict__ Wq,
    const float* __restrict__ Wv)
{
    __shared__ float xs[64][33];   // stride 33 -> conflict-free strided row reads
    __shared__ float ws[32][64];

    const float* W;
    float* dst;
    if (blockIdx.y == 0)      { W = Wq; dst = g_q; }
    else if (blockIdx.y == 1) { W = Wk; dst = g_k; }
    else                      { W = Wv; dst = g_v; }

    const int tid = threadIdx.x;
    const int tx = tid & 15, ty = tid >> 4;
    const int row0 = blockIdx.x * 64;

    float acc[4][4] = {};

    for (int k0 = 0; k0 < C; k0 += 32) {
        __syncthreads();
        #pragma unroll
        for (int t = 0; t < 2; t++) {
            int f = tid * 2 + t;                   // 0..511 float4 slots
            // x tile: 64 rows x 32 cols
            int r = f >> 3;
            int c = (f & 7) * 4;
            float4 v4 = *reinterpret_cast<const float4*>(
                x + (size_t)(row0 + r) * C + k0 + c);
            xs[r][c + 0] = v4.x; xs[r][c + 1] = v4.y;
            xs[r][c + 2] = v4.z; xs[r][c + 3] = v4.w;
            // W tile: 32 rows x 64 cols
            int r2 = f >> 4;
            int c2 = (f & 15) * 4;
            *reinterpret_cast<float4*>(&ws[r2][c2]) =
                *reinterpret_cast<const float4*>(W + (size_t)(k0 + r2) * HS + c2);
        }
        __syncthreads();

        #pragma unroll
        for (int kk = 0; kk < 32; kk++) {
            float a[4];
            #pragma unroll
            for (int i = 0; i < 4; i++) a[i] = xs[ty + 16 * i][kk];
            float4 b4 = *reinterpret_cast<float4*>(&ws[kk][tx * 4]);
            float bb[4] = {b4.x, b4.y, b4.z, b4.w};
            #pragma unroll
            for (int i = 0; i < 4; i++)
                #pragma unroll
                for (int j = 0; j < 4; j++)
                    acc[i][j] = fmaf(a[i], bb[j], acc[i][j]);
        }
    }

    #pragma unroll
    for (int i = 0; i < 4; i++) {
        int r = row0 + ty + 16 * i;
        #pragma unroll
        for (int j = 0; j < 4; j++)
            dst[(size_t)r * HS + tx * 4 + j] = acc[i][j];
    }
}

// ---------------------------------------------------------------------------
// Flash attention, causal. BR = BC = 64, HS = 64, block = 256 threads.
// Thread (ty,tx): query rows {ty+16i}, key cols / out dims {tx+16j}.
// All hot-loop smem accesses are bank-conflict-free with stride 65.
// Row softmax stats reduced across the 16 tx lanes (shfl_xor 8,4,2,1).
// grid = (TR, B); qt zigzag-mapped for causal load balance.
// ---------------------------------------------------------------------------
__global__ __launch_bounds__(256) void flash_kernel(float* __restrict__ out)
{
    extern __shared__ float sm[];
    float* Qs = sm;                 // [64][65]
    float* Ks = sm + 64 * 65;       // [64][65]
    float* Vs = sm + 2 * 64 * 65;   // [64][65]
    float* Ps = sm + 3 * 64 * 65;   // [64][65]

    const int bx = blockIdx.x;
    const int pp = bx >> 1;
    const int qt = (bx & 1) ? pp : (TR - 1 - pp);   // 63,0,62,1,...
    const int b  = blockIdx.y;
    const int tid = threadIdx.x;
    const int tx = tid & 15, ty = tid >> 4;

    // Load Q tile (64x64) into smem, stride-65
    const float* qg = g_q + (size_t)(b * T + qt * 64) * HS;
    #pragma unroll
    for (int t = 0; t < 4; t++) {
        int f = tid + 256 * t;          // 1024 float4 slots
        int r = f >> 4;
        int c = (f & 15) * 4;
        float4 v4 = *reinterpret_cast<const float4*>(qg + r * HS + c);
        Qs[r * 65 + c + 0] = v4.x; Qs[r * 65 + c + 1] = v4.y;
        Qs[r * 65 + c + 2] = v4.z; Qs[r * 65 + c + 3] = v4.w;
    }

    float o[4][4] = {};
    float m[4], l[4];
    #pragma unroll
    for (int i = 0; i < 4; i++) { m[i] = -1e30f; l[i] = 0.f; }

    for (int kb = 0; kb <= qt; kb++) {
        __syncthreads();   // previous PV done before overwriting Ks/Vs
        const float* kg = g_k + (size_t)(b * T + kb * 64) * HS;
        const float* vg = g_v + (size_t)(b * T + kb * 64) * HS;
        #pragma unroll
        for (int t = 0; t < 4; t++) {
            int f = tid + 256 * t;
            int r = f >> 4;
            int c = (f & 15) * 4;
            float4 kv = *reinterpret_cast<const float4*>(kg + r * HS + c);
            Ks[r * 65 + c + 0] = kv.x; Ks[r * 65 + c + 1] = kv.y;
            Ks[r * 65 + c + 2] = kv.z; Ks[r * 65 + c + 3] = kv.w;
            float4 vv = *reinterpret_cast<const float4*>(vg + r * HS + c);
            Vs[r * 65 + c + 0] = vv.x; Vs[r * 65 + c + 1] = vv.y;
            Vs[r * 65 + c + 2] = vv.z; Vs[r * 65 + c + 3] = vv.w;
        }
        __syncthreads();

        // S = Q @ K^T  (4x4 per thread)
        float s[4][4] = {};
        #pragma unroll 8
        for (int kk = 0; kk < 64; kk++) {
            float a[4], bb[4];
            #pragma unroll
            for (int i = 0; i < 4; i++) a[i] = Qs[(ty + 16 * i) * 65 + kk];
            #pragma unroll
            for (int j = 0; j < 4; j++) bb[j] = Ks[(tx + 16 * j) * 65 + kk];
            #pragma unroll
            for (int i = 0; i < 4; i++)
                #pragma unroll
                for (int j = 0; j < 4; j++)
                    s[i][j] = fmaf(a[i], bb[j], s[i][j]);
        }

        // scale + causal mask (only diagonal tile needs masking)
        const bool diag = (kb == qt);
        #pragma unroll
        for (int i = 0; i < 4; i++) {
            int rloc = ty + 16 * i;
            #pragma unroll
            for (int j = 0; j < 4; j++) {
                s[i][j] *= 0.125f;   // hs^-0.5
                if (diag && (tx + 16 * j) > rloc) s[i][j] = -1e30f;
            }
        }

        // online softmax per row
        #pragma unroll
        for (int i = 0; i < 4; i++) {
            float mt = fmaxf(fmaxf(s[i][0], s[i][1]), fmaxf(s[i][2], s[i][3]));
            #pragma unroll
            for (int off = 8; off >= 1; off >>= 1)
                mt = fmaxf(mt, __shfl_xor_sync(0xffffffffu, mt, off));
            float mnew = fmaxf(m[i], mt);
            float rs = 0.f;
            #pragma unroll
            for (int j = 0; j < 4; j++) {
                float pv = exp2f((s[i][j] - mnew) * LOG2E);
                s[i][j] = pv;
                rs += pv;
            }
            #pragma unroll
            for (int off = 8; off >= 1; off >>= 1)
                rs += __shfl_xor_sync(0xffffffffu, rs, off);
            float alpha = exp2f((m[i] - mnew) * LOG2E);
            l[i] = l[i] * alpha + rs;
            m[i] = mnew;
            #pragma unroll
            for (int j = 0; j < 4; j++) o[i][j] *= alpha;
            #pragma unroll
            for (int j = 0; j < 4; j++)
                Ps[(ty + 16 * i) * 65 + tx + 16 * j] = s[i][j];
        }
        __syncthreads();   // P fully written before PV reads

        // O += P @ V
        #pragma unroll 8
        for (int c = 0; c < 64; c++) {
            float a[4], bb[4];
            #pragma unroll
            for (int i = 0; i < 4; i++) a[i] = Ps[(ty + 16 * i) * 65 + c];
            #pragma unroll
            for (int j = 0; j < 4; j++) bb[j] = Vs[c * 65 + tx + 16 * j];
            #pragma unroll
            for (int i = 0; i < 4; i++)
                #pragma unroll
                for (int j = 0; j < 4; j++)
                    o[i][j] = fmaf(a[i], bb[j], o[i][j]);
        }
    }

    // epilogue: out = O / l
    float* og = out + (size_t)(b * T + qt * 64) * HS;
    #pragma unroll
    for (int i = 0; i < 4; i++) {
        float inv = 1.f / l[i];
        #pragma unroll
        for (int j = 0; j < 4; j++)
            og[(ty + 16 * i) * HS + tx + 16 * j] = o[i][j] * inv;
    }
}

// ---------------------------------------------------------------------------
// kernel_launch: inputs per metadata order: x, Wk, Wq, Wv. Output fp32 [B,T,HS].
// ---------------------------------------------------------------------------
extern "C" void kernel_launch(void* const* d_in, const int* in_sizes, int n_in,
                              void* d_out, int out_size)
{
    const float* x  = (const float*)d_in[0];
    const float* Wk = (const float*)d_in[1];
    const float* Wq = (const float*)d_in[2];
    const float* Wv = (const float*)d_in[3];
    float* out = (float*)d_out;

    // Idempotent, capture-safe (not a stream op).
    cudaFuncSetAttribute(flash_kernel,
                         cudaFuncAttributeMaxDynamicSharedMemorySize, FLASH_SMEM);

    proj_kernel<<<dim3((B * T) / 64, 3), 256>>>(x, Wk, Wq, Wv);
    flash_kernel<<<dim3(TR, B), 256, FLASH_SMEM>>>(out);
}

// round 7
// speedup vs baseline: 3.2992x; 3.2992x over previous
#include <cuda_runtime.h>
#include <cstdint>

// Problem constants
constexpr int B  = 4;
constexpr int T  = 4096;
constexpr int C  = 512;
constexpr int HS = 64;
// Q pre-scale folded into projection: (1/sqrt(64)) * log2(e)
constexpr float QSCALE = 0.18033688011112042f;

// Scratch — __device__ globals, no allocation.
__device__ __align__(16) float g_q[B * T * HS];   // tf32-rounded, pre-scaled
__device__ __align__(16) float g_k[B * T * HS];   // tf32-rounded
__device__ __align__(16) float g_v[B * T * HS];   // tf32-rounded
__device__ __align__(16) float g_vt[B * T * HS];  // [b][tile][dim][key] transposed

// ---------------------------------------------------------------------------
// Helpers (sm_80-level PTX only — safe for compute_100 baseline target)
// ---------------------------------------------------------------------------
__device__ __forceinline__ float cvt_tf32(float x) {
    uint32_t y;                        // tf32 cvt destination must be .b32
    asm("cvt.rna.tf32.f32 %0, %1;" : "=r"(y) : "f"(x));
    return __uint_as_float(y);
}
__device__ __forceinline__ float fast_exp2(float x) {
    float y;
    asm("ex2.approx.f32 %0, %1;" : "=f"(y) : "f"(x));
    return y;
}
__device__ __forceinline__ void cp16(uint32_t dst, const void* src) {
    asm volatile("cp.async.cg.shared.global [%0], [%1], 16;" :: "r"(dst), "l"(src));
}
#define CP_COMMIT() asm volatile("cp.async.commit_group;" ::: "memory")
#define CP_WAIT(n)  asm volatile("cp.async.wait_group %0;" :: "n"(n) : "memory")

__device__ __forceinline__ void ldm4(uint32_t& r0, uint32_t& r1, uint32_t& r2,
                                     uint32_t& r3, uint32_t addr) {
    asm volatile("ldmatrix.sync.aligned.m8n8.x4.shared.b16 {%0,%1,%2,%3}, [%4];"
                 : "=r"(r0), "=r"(r1), "=r"(r2), "=r"(r3) : "r"(addr));
}
// D(16x8,f32) += A(16x8,tf32) * B(8x8,tf32)
__device__ __forceinline__ void mma8(float* d, const uint32_t* a, const uint32_t* b) {
    asm volatile(
        "mma.sync.aligned.m16n8k8.row.col.f32.tf32.tf32.f32 "
        "{%0,%1,%2,%3},{%4,%5,%6,%7},{%8,%9},{%0,%1,%2,%3};"
        : "+f"(d[0]), "+f"(d[1]), "+f"(d[2]), "+f"(d[3])
        : "r"(a[0]), "r"(a[1]), "r"(a[2]), "r"(a[3]), "r"(b[0]), "r"(b[1]));
}

// ---------------------------------------------------------------------------
// Projection: dst[M,64] = x[M,512] @ W[512,64], epilogue rounds to tf32
// (q additionally pre-scaled by QSCALE).  [identical to R5]
// ---------------------------------------------------------------------------
__global__ __launch_bounds__(256) void proj_kernel(
    const float* __restrict__ x,
    const float* __restrict__ Wk,
    const float* __restrict__ Wq,
    const float* __restrict__ Wv)
{
    __shared__ float xs[64][33];
    __shared__ float ws[32][64];

    const float* W;
    float* dst;
    float sc;
    if (blockIdx.y == 0)      { W = Wq; dst = g_q; sc = QSCALE; }
    else if (blockIdx.y == 1) { W = Wk; dst = g_k; sc = 1.f; }
    else                      { W = Wv; dst = g_v; sc = 1.f; }

    const int tid = threadIdx.x;
    const int tx = tid & 15, ty = tid >> 4;
    const int row0 = blockIdx.x * 64;

    float acc[4][4] = {};

    for (int k0 = 0; k0 < C; k0 += 32) {
        __syncthreads();
        #pragma unroll
        for (int t = 0; t < 2; t++) {
            int f = tid * 2 + t;
            int r = f >> 3;
            int c = (f & 7) * 4;
            float4 v4 = *reinterpret_cast<const float4*>(
                x + (size_t)(row0 + r) * C + k0 + c);
            xs[r][c + 0] = v4.x; xs[r][c + 1] = v4.y;
            xs[r][c + 2] = v4.z; xs[r][c + 3] = v4.w;
            int r2 = f >> 4;
            int c2 = (f & 15) * 4;
            *reinterpret_cast<float4*>(&ws[r2][c2]) =
                *reinterpret_cast<const float4*>(W + (size_t)(k0 + r2) * HS + c2);
        }
        __syncthreads();

        #pragma unroll
        for (int kk = 0; kk < 32; kk++) {
            float a[4];
            #pragma unroll
            for (int i = 0; i < 4; i++) a[i] = xs[ty + 16 * i][kk];
            float4 b4 = *reinterpret_cast<float4*>(&ws[kk][tx * 4]);
            float bb[4] = {b4.x, b4.y, b4.z, b4.w};
            #pragma unroll
            for (int i = 0; i < 4; i++)
                #pragma unroll
                for (int j = 0; j < 4; j++)
                    acc[i][j] = fmaf(a[i], bb[j], acc[i][j]);
        }
    }

    #pragma unroll
    for (int i = 0; i < 4; i++) {
        int r = row0 + ty + 16 * i;
        #pragma unroll
        for (int j = 0; j < 4; j++)
            dst[(size_t)r * HS + tx * 4 + j] = cvt_tf32(acc[i][j] * sc);
    }
}

// ---------------------------------------------------------------------------
// V transpose: g_vt[b][tile][dim][key] = g_v[b][tile*64+key][dim]
// [identical to R5]
// ---------------------------------------------------------------------------
__global__ __launch_bounds__(256) void vtrans_kernel()
{
    __shared__ float ts[64 * 65];
    const int tile = blockIdx.x, b = blockIdx.y;
    const int tid = threadIdx.x;
    const float* src = g_v + ((size_t)b * T + tile * 64) * HS;
    #pragma unroll
    for (int t = 0; t < 4; t++) {
        int f = tid + 256 * t;          // 1024 float4 chunks
        int key = f >> 4, dc = f & 15;
        float4 v = *reinterpret_cast<const float4*>(src + key * 64 + dc * 4);
        ts[key * 65 + dc * 4 + 0] = v.x;
        ts[key * 65 + dc * 4 + 1] = v.y;
        ts[key * 65 + dc * 4 + 2] = v.z;
        ts[key * 65 + dc * 4 + 3] = v.w;
    }
    __syncthreads();
    float* dst = g_vt + ((size_t)b * T + tile * 64) * HS;
    #pragma unroll
    for (int t = 0; t < 4; t++) {
        int f = tid + 256 * t;
        int kc = f & 15, dim = f >> 4;
        float4 w;
        w.x = ts[(4 * kc + 0) * 65 + dim];
        w.y = ts[(4 * kc + 1) * 65 + dim];
        w.z = ts[(4 * kc + 2) * 65 + dim];
        w.w = ts[(4 * kc + 3) * 65 + dim];
        *reinterpret_cast<float4*>(dst + dim * 64 + kc * 4) = w;
    }
}

// ---------------------------------------------------------------------------
// Flash attention via mma.sync tf32 — R5 arithmetic, fixed pipelining.
// BR=BC=64, 4 warps, warp owns 16 q-rows. CTA c handles q-tiles {c, 63-c}.
// Race fix (the ONLY change vs R5): each iteration does
//   CP_WAIT(0); __syncthreads();            // my copies done + all warps'
//                                           //   prior-iteration reads done
//   prefetch(next) into the OTHER buffer;   // safe to overwrite now
//   compute from the CURRENT buffer.
// ---------------------------------------------------------------------------
constexpr int KSTRIDE_B = 272;                 // bytes per smem row (68 floats)
constexpr int TILE_SM   = 64 * KSTRIDE_B;      // 17408 B
constexpr int SM_K0 = 0, SM_K1 = TILE_SM, SM_V0 = 2 * TILE_SM, SM_V1 = 3 * TILE_SM;
constexpr int FLASH_SMEM = 4 * TILE_SM;        // 69632 B

__global__ __launch_bounds__(128, 1) void flash_mma(float* __restrict__ out)
{
    extern __shared__ char sm[];
    const uint32_t smb = (uint32_t)__cvta_generic_to_shared(sm);
    const int tid = threadIdx.x;
    const int wid = tid >> 5, lane = tid & 31;
    const int gid = lane >> 2, qd = lane & 3;
    const int cta = blockIdx.x, b = blockIdx.y;

    const float* kb_base = g_k  + (size_t)b * T * HS;
    const float* vt_base = g_vt + (size_t)b * T * HS;

    const int qts[2] = {cta, 63 - cta};

    // ldmatrix per-lane row/offset (same pattern for K and VT tiles)
    const int lrow = ((lane >> 4) & 1) * 8 + (lane & 7);
    const int lofs = ((lane >> 3) & 1) * 16;

    int step = 0;

    auto prefetch = [&](int kb, int pbuf) {
        uint32_t dK = smb + (pbuf ? SM_K1 : SM_K0);
        uint32_t dV = smb + (pbuf ? SM_V1 : SM_V0);
        const float* sk = kb_base + (size_t)kb * 64 * HS;
        const float* sv = vt_base + (size_t)kb * 64 * HS;
        #pragma unroll
        for (int t = 0; t < 8; t++) {
            int f = tid + 128 * t;              // 1024 chunks each
            int r = f >> 4, c = f & 15;
            cp16(dK + r * KSTRIDE_B + c * 16, sk + r * 64 + c * 4);
            cp16(dV + r * KSTRIDE_B + c * 16, sv + r * 64 + c * 4);
        }
        CP_COMMIT();
    };

    prefetch(0, 0);   // phase 0, kb = 0

    for (int ph = 0; ph < 2; ph++) {
        const int qt = qts[ph];

        // Q fragments (tf32-rounded + scaled in proj)
        uint32_t qf[8][4];
        const float* qg = g_q + ((size_t)b * T + qt * 64 + 16 * wid) * HS;
        #pragma unroll
        for (int k = 0; k < 8; k++) {
            qf[k][0] = __float_as_uint(__ldg(qg + (gid    ) * 64 + k * 8 + qd    ));
            qf[k][1] = __float_as_uint(__ldg(qg + (gid + 8) * 64 + k * 8 + qd    ));
            qf[k][2] = __float_as_uint(__ldg(qg + (gid    ) * 64 + k * 8 + qd + 4));
            qf[k][3] = __float_as_uint(__ldg(qg + (gid + 8) * 64 + k * 8 + qd + 4));
        }

        float O[8][4];
        #pragma unroll
        for (int nt = 0; nt < 8; nt++)
            #pragma unroll
            for (int e = 0; e < 4; e++) O[nt][e] = 0.f;
        float l0 = 0.f, l1 = 0.f;

        const int rowg0 = qt * 64 + 16 * wid + gid;

        for (int kb = 0; kb <= qt; kb++) {
            const int cur = step & 1;

            // My cp.async for buffer `cur` complete; barrier makes all
            // threads' copies visible AND orders every warp's reads of the
            // other buffer (previous iteration) before we overwrite it.
            CP_WAIT(0);
            __syncthreads();

            const bool hasnext = (kb < qt) || (ph == 0);
            if (hasnext) {
                const int nkb = (kb < qt) ? kb + 1 : 0;
                prefetch(nkb, cur ^ 1);
            }

            const uint32_t ksm = smb + (cur ? SM_K1 : SM_K0);
            const uint32_t vsm = smb + (cur ? SM_V1 : SM_V0);

            // ---- S = Q @ K^T ----
            float S[8][4];
            #pragma unroll
            for (int nt = 0; nt < 8; nt++)
                #pragma unroll
                for (int e = 0; e < 4; e++) S[nt][e] = 0.f;

            #pragma unroll
            for (int k = 0; k < 8; k++) {
                uint32_t bf[8][2];
                #pragma unroll
                for (int g = 0; g < 4; g++) {
                    uint32_t addr = ksm + (16 * g + lrow) * KSTRIDE_B + lofs + k * 32;
                    ldm4(bf[2*g][0], bf[2*g][1], bf[2*g+1][0], bf[2*g+1][1], addr);
                }
                #pragma unroll
                for (int nt = 0; nt < 8; nt++) mma8(S[nt], qf[k], bf[nt]);
            }

            // ---- softmax (shift-free) + tf32 rounding; l from rounded P ----
            const bool diag = (kb == qt);
            const int col0g = kb * 64;
            #pragma unroll
            for (int nt = 0; nt < 8; nt++) {
                float p0 = fast_exp2(S[nt][0]);
                float p1 = fast_exp2(S[nt][1]);
                float p2 = fast_exp2(S[nt][2]);
                float p3 = fast_exp2(S[nt][3]);
                if (diag) {
                    int cb = col0g + 8 * nt + 2 * qd;
                    if (cb     > rowg0)     p0 = 0.f;
                    if (cb + 1 > rowg0)     p1 = 0.f;
                    if (cb     > rowg0 + 8) p2 = 0.f;
                    if (cb + 1 > rowg0 + 8) p3 = 0.f;
                }
                p0 = cvt_tf32(p0); p1 = cvt_tf32(p1);
                p2 = cvt_tf32(p2); p3 = cvt_tf32(p3);
                l0 += p0 + p1;
                l1 += p2 + p3;
                S[nt][0] = p0; S[nt][1] = p1; S[nt][2] = p2; S[nt][3] = p3;
            }

            // ---- P: D-frag -> A-frag permutation (in-warp) ----
            uint32_t pf[8][4];
            const int base = lane & ~3;
            const int s0 = base + (qd >> 1);
            const int s2 = s0 + 2;
            const bool odd = (qd & 1);
            #pragma unroll
            for (int nt = 0; nt < 8; nt++) {
                float x0 = __shfl_sync(0xffffffffu, S[nt][0], s0);
                float x1 = __shfl_sync(0xffffffffu, S[nt][1], s0);
                float y0 = __shfl_sync(0xffffffffu, S[nt][2], s0);
                float y1 = __shfl_sync(0xffffffffu, S[nt][3], s0);
                float x2 = __shfl_sync(0xffffffffu, S[nt][0], s2);
                float x3 = __shfl_sync(0xffffffffu, S[nt][1], s2);
                float y2 = __shfl_sync(0xffffffffu, S[nt][2], s2);
                float y3 = __shfl_sync(0xffffffffu, S[nt][3], s2);
                pf[nt][0] = __float_as_uint(odd ? x1 : x0);
                pf[nt][1] = __float_as_uint(odd ? y1 : y0);
                pf[nt][2] = __float_as_uint(odd ? x3 : x2);
                pf[nt][3] = __float_as_uint(odd ? y3 : y2);
            }

            // ---- O += P @ V (VT is dim-major) ----
            #pragma unroll
            for (int k = 0; k < 8; k++) {
                uint32_t bf[8][2];
                #pragma unroll
                for (int g = 0; g < 4; g++) {
                    uint32_t addr = vsm + (16 * g + lrow) * KSTRIDE_B + lofs + k * 32;
                    ldm4(bf[2*g][0], bf[2*g][1], bf[2*g+1][0], bf[2*g+1][1], addr);
                }
                #pragma unroll
                for (int nt = 0; nt < 8; nt++) mma8(O[nt], pf[k], bf[nt]);
            }
            step++;
        }

        // ---- epilogue: reduce l over quad, normalize, store ----
        l0 += __shfl_xor_sync(0xffffffffu, l0, 1);
        l0 += __shfl_xor_sync(0xffffffffu, l0, 2);
        l1 += __shfl_xor_sync(0xffffffffu, l1, 1);
        l1 += __shfl_xor_sync(0xffffffffu, l1, 2);
        const float inv0 = 1.f / l0, inv1 = 1.f / l1;

        float* og = out + ((size_t)b * T + qt * 64 + 16 * wid) * HS;
        #pragma unroll
        for (int nt = 0; nt < 8; nt++) {
            int c0 = 8 * nt + 2 * qd;
            float2 lo = make_float2(O[nt][0] * inv0, O[nt][1] * inv0);
            float2 hi = make_float2(O[nt][2] * inv1, O[nt][3] * inv1);
            *reinterpret_cast<float2*>(og + (gid    ) * 64 + c0) = lo;
            *reinterpret_cast<float2*>(og + (gid + 8) * 64 + c0) = hi;
        }
    }
}

// ---------------------------------------------------------------------------
extern "C" void kernel_launch(void* const* d_in, const int* in_sizes, int n_in,
                              void* d_out, int out_size)
{
    const float* x  = (const float*)d_in[0];
    const float* Wk = (const float*)d_in[1];
    const float* Wq = (const float*)d_in[2];
    const float* Wv = (const float*)d_in[3];
    float* out = (float*)d_out;

    cudaFuncSetAttribute(flash_mma,
                         cudaFuncAttributeMaxDynamicSharedMemorySize, FLASH_SMEM);

    proj_kernel<<<dim3((B * T) / 64, 3), 256>>>(x, Wk, Wq, Wv);
    vtrans_kernel<<<dim3(T / 64, B), 256>>>();
    flash_mma<<<dim3(32, B), 128, FLASH_SMEM>>>(out);
}

// round 9
// speedup vs baseline: 3.8983x; 1.1816x over previous
#include <cuda_runtime.h>
#include <cstdint>

// Problem constants
constexpr int B  = 4;
constexpr int T  = 4096;
constexpr int C  = 512;
constexpr int HS = 64;
// Q pre-scale folded into projection: (1/sqrt(64)) * log2(e)
constexpr float QSCALE = 0.18033688011112042f;

// Scratch — __device__ globals, no allocation.
__device__ __align__(16) float g_q[B * T * HS];   // tf32-rounded, pre-scaled
__device__ __align__(16) float g_k[B * T * HS];   // tf32-rounded
__device__ __align__(16) float g_vt[B * T * HS];  // [b][tile][dim][key], tf32-rounded

// ---------------------------------------------------------------------------
// Helpers (sm_80-level PTX only — safe for compute_100 baseline target)
// ---------------------------------------------------------------------------
__device__ __forceinline__ float cvt_tf32(float x) {
    uint32_t y;                        // tf32 cvt destination must be .b32
    asm("cvt.rna.tf32.f32 %0, %1;" : "=r"(y) : "f"(x));
    return __uint_as_float(y);
}
__device__ __forceinline__ float fast_exp2(float x) {
    float y;
    asm("ex2.approx.f32 %0, %1;" : "=f"(y) : "f"(x));
    return y;
}
__device__ __forceinline__ void cp16(uint32_t dst, const void* src) {
    asm volatile("cp.async.cg.shared.global [%0], [%1], 16;" :: "r"(dst), "l"(src));
}
#define CP_COMMIT() asm volatile("cp.async.commit_group;" ::: "memory")
#define CP_WAIT(n)  asm volatile("cp.async.wait_group %0;" :: "n"(n) : "memory")

__device__ __forceinline__ void ldm4(uint32_t& r0, uint32_t& r1, uint32_t& r2,
                                     uint32_t& r3, uint32_t addr) {
    asm volatile("ldmatrix.sync.aligned.m8n8.x4.shared.b16 {%0,%1,%2,%3}, [%4];"
                 : "=r"(r0), "=r"(r1), "=r"(r2), "=r"(r3) : "r"(addr));
}
// D(16x8,f32) += A(16x8,tf32) * B(8x8,tf32)
__device__ __forceinline__ void mma8(float* d, const uint32_t* a, const uint32_t* b) {
    asm volatile(
        "mma.sync.aligned.m16n8k8.row.col.f32.tf32.tf32.f32 "
        "{%0,%1,%2,%3},{%4,%5,%6,%7},{%8,%9},{%0,%1,%2,%3};"
        : "+f"(d[0]), "+f"(d[1]), "+f"(d[2]), "+f"(d[3])
        : "r"(a[0]), "r"(a[1]), "r"(a[2]), "r"(a[3]), "r"(b[0]), "r"(b[1]));
}

// ---------------------------------------------------------------------------
// Fused projection: one pass over x computes q, k, v (x loaded ONCE).
//   q = tf32(x@Wq * QSCALE)   -> g_q   (row-major)
//   k = tf32(x@Wk)            -> g_k   (row-major)
//   v = tf32(x@Wv)            -> g_vt  (TRANSPOSED per 64-row tile, [dim][key])
// grid = 256 CTAs (one 64-row tile each), block = 256. All CTAs co-resident
// at 2 CTAs/SM -> single wave.
// ---------------------------------------------------------------------------
__global__ __launch_bounds__(256) void proj_fused(
    const float* __restrict__ x,
    const float* __restrict__ Wk,
    const float* __restrict__ Wq,
    const float* __restrict__ Wv)
{
    __shared__ float xs[64][33];        // 8.4 KB
    __shared__ float ws[3][32][64];     // 24 KB; reused as ts[64*65] in epilogue

    const int tid = threadIdx.x;
    const int tx = tid & 15, ty = tid >> 4;
    const int row0 = blockIdx.x * 64;

    const float* Wm[3] = {Wq, Wk, Wv};

    float acc[3][4][4] = {};

    for (int k0 = 0; k0 < C; k0 += 32) {
        __syncthreads();
        // x tile: 64 rows x 32 cols (512 float4 slots, 2/thread)
        #pragma unroll
        for (int t = 0; t < 2; t++) {
            int f = tid * 2 + t;
            int r = f >> 3;
            int c = (f & 7) * 4;
            float4 v4 = *reinterpret_cast<const float4*>(
                x + (size_t)(row0 + r) * C + k0 + c);
            xs[r][c + 0] = v4.x; xs[r][c + 1] = v4.y;
            xs[r][c + 2] = v4.z; xs[r][c + 3] = v4.w;
        }
        // W tiles: 3 x (32 rows x 64 cols), 512 float4 slots each, 2/thread
        #pragma unroll
        for (int w = 0; w < 3; w++) {
            #pragma unroll
            for (int t = 0; t < 2; t++) {
                int f = tid * 2 + t;
                int r2 = f >> 4;
                int c2 = (f & 15) * 4;
                *reinterpret_cast<float4*>(&ws[w][r2][c2]) =
                    *reinterpret_cast<const float4*>(
                        Wm[w] + (size_t)(k0 + r2) * HS + c2);
            }
        }
        __syncthreads();

        #pragma unroll 8
        for (int kk = 0; kk < 32; kk++) {
            float a[4];
            #pragma unroll
            for (int i = 0; i < 4; i++) a[i] = xs[ty + 16 * i][kk];
            #pragma unroll
            for (int w = 0; w < 3; w++) {
                float4 b4 = *reinterpret_cast<float4*>(&ws[w][kk][tx * 4]);
                float bb[4] = {b4.x, b4.y, b4.z, b4.w};
                #pragma unroll
                for (int i = 0; i < 4; i++)
                    #pragma unroll
                    for (int j = 0; j < 4; j++)
                        acc[w][i][j] = fmaf(a[i], bb[j], acc[w][i][j]);
            }
        }
    }

    // ---- q, k: direct row-major stores ----
    #pragma unroll
    for (int i = 0; i < 4; i++) {
        int r = row0 + ty + 16 * i;
        #pragma unroll
        for (int j = 0; j < 4; j++) {
            g_q[(size_t)r * HS + tx * 4 + j] = cvt_tf32(acc[0][i][j] * QSCALE);
            g_k[(size_t)r * HS + tx * 4 + j] = cvt_tf32(acc[1][i][j]);
        }
    }

    // ---- v: stage in smem (reuse ws), then transposed store to g_vt ----
    float* ts = &ws[0][0][0];           // 4160 floats needed <= 6144 available
    __syncthreads();                    // all ws reads in k-loop are done
    #pragma unroll
    for (int i = 0; i < 4; i++) {
        int rl = ty + 16 * i;           // local row (key) 0..63
        #pragma unroll
        for (int j = 0; j < 4; j++)
            ts[rl * 65 + tx * 4 + j] = cvt_tf32(acc[2][i][j]);
    }
    __syncthreads();
    float* dst = g_vt + (size_t)row0 * HS;   // == (b*T + tile*64) * HS
    #pragma unroll
    for (int t = 0; t < 4; t++) {
        int f = tid + 256 * t;          // 1024 float4 chunks
        int kc = f & 15, dim = f >> 4;
        float4 w4;
        w4.x = ts[(4 * kc + 0) * 65 + dim];
        w4.y = ts[(4 * kc + 1) * 65 + dim];
        w4.z = ts[(4 * kc + 2) * 65 + dim];
        w4.w = ts[(4 * kc + 3) * 65 + dim];
        *reinterpret_cast<float4*>(dst + dim * 64 + kc * 4) = w4;
    }
}

// ---------------------------------------------------------------------------
// Flash attention via mma.sync tf32 — IDENTICAL to R7 (passing) kernel.
// BR=BC=64, 4 warps, warp owns 16 q-rows. CTA c handles q-tiles {c, 63-c}.
// ---------------------------------------------------------------------------
constexpr int KSTRIDE_B = 272;                 // bytes per smem row (68 floats)
constexpr int TILE_SM   = 64 * KSTRIDE_B;      // 17408 B
constexpr int SM_K0 = 0, SM_K1 = TILE_SM, SM_V0 = 2 * TILE_SM, SM_V1 = 3 * TILE_SM;
constexpr int FLASH_SMEM = 4 * TILE_SM;        // 69632 B

__global__ __launch_bounds__(128, 1) void flash_mma(float* __restrict__ out)
{
    extern __shared__ char sm[];
    const uint32_t smb = (uint32_t)__cvta_generic_to_shared(sm);
    const int tid = threadIdx.x;
    const int wid = tid >> 5, lane = tid & 31;
    const int gid = lane >> 2, qd = lane & 3;
    const int cta = blockIdx.x, b = blockIdx.y;

    const float* kb_base = g_k  + (size_t)b * T * HS;
    const float* vt_base = g_vt + (size_t)b * T * HS;

    const int qts[2] = {cta, 63 - cta};

    const int lrow = ((lane >> 4) & 1) * 8 + (lane & 7);
    const int lofs = ((lane >> 3) & 1) * 16;

    int step = 0;

    auto prefetch = [&](int kb, int pbuf) {
        uint32_t dK = smb + (pbuf ? SM_K1 : SM_K0);
        uint32_t dV = smb + (pbuf ? SM_V1 : SM_V0);
        const float* sk = kb_base + (size_t)kb * 64 * HS;
        const float* sv = vt_base + (size_t)kb * 64 * HS;
        #pragma unroll
        for (int t = 0; t < 8; t++) {
            int f = tid + 128 * t;              // 1024 chunks each
            int r = f >> 4, c = f & 15;
            cp16(dK + r * KSTRIDE_B + c * 16, sk + r * 64 + c * 4);
            cp16(dV + r * KSTRIDE_B + c * 16, sv + r * 64 + c * 4);
        }
        CP_COMMIT();
    };

    prefetch(0, 0);   // phase 0, kb = 0

    for (int ph = 0; ph < 2; ph++) {
        const int qt = qts[ph];

        uint32_t qf[8][4];
        const float* qg = g_q + ((size_t)b * T + qt * 64 + 16 * wid) * HS;
        #pragma unroll
        for (int k = 0; k < 8; k++) {
            qf[k][0] = __float_as_uint(__ldg(qg + (gid    ) * 64 + k * 8 + qd    ));
            qf[k][1] = __float_as_uint(__ldg(qg + (gid + 8) * 64 + k * 8 + qd    ));
            qf[k][2] = __float_as_uint(__ldg(qg + (gid    ) * 64 + k * 8 + qd + 4));
            qf[k][3] = __float_as_uint(__ldg(qg + (gid + 8) * 64 + k * 8 + qd + 4));
        }

        float O[8][4];
        #pragma unroll
        for (int nt = 0; nt < 8; nt++)
            #pragma unroll
            for (int e = 0; e < 4; e++) O[nt][e] = 0.f;
        float l0 = 0.f, l1 = 0.f;

        const int rowg0 = qt * 64 + 16 * wid + gid;

        for (int kb = 0; kb <= qt; kb++) {
            const int cur = step & 1;

            CP_WAIT(0);
            __syncthreads();

            const bool hasnext = (kb < qt) || (ph == 0);
            if (hasnext) {
                const int nkb = (kb < qt) ? kb + 1 : 0;
                prefetch(nkb, cur ^ 1);
            }

            const uint32_t ksm = smb + (cur ? SM_K1 : SM_K0);
            const uint32_t vsm = smb + (cur ? SM_V1 : SM_V0);

            // ---- S = Q @ K^T ----
            float S[8][4];
            #pragma unroll
            for (int nt = 0; nt < 8; nt++)
                #pragma unroll
                for (int e = 0; e < 4; e++) S[nt][e] = 0.f;

            #pragma unroll
            for (int k = 0; k < 8; k++) {
                uint32_t bf[8][2];
                #pragma unroll
                for (int g = 0; g < 4; g++) {
                    uint32_t addr = ksm + (16 * g + lrow) * KSTRIDE_B + lofs + k * 32;
                    ldm4(bf[2*g][0], bf[2*g][1], bf[2*g+1][0], bf[2*g+1][1], addr);
                }
                #pragma unroll
                for (int nt = 0; nt < 8; nt++) mma8(S[nt], qf[k], bf[nt]);
            }

            // ---- softmax (shift-free) + tf32 rounding; l from rounded P ----
            const bool diag = (kb == qt);
            const int col0g = kb * 64;
            #pragma unroll
            for (int nt = 0; nt < 8; nt++) {
                float p0 = fast_exp2(S[nt][0]);
                float p1 = fast_exp2(S[nt][1]);
                float p2 = fast_exp2(S[nt][2]);
                float p3 = fast_exp2(S[nt][3]);
                if (diag) {
                    int cb = col0g + 8 * nt + 2 * qd;
                    if (cb     > rowg0)     p0 = 0.f;
                    if (cb + 1 > rowg0)     p1 = 0.f;
                    if (cb     > rowg0 + 8) p2 = 0.f;
                    if (cb + 1 > rowg0 + 8) p3 = 0.f;
                }
                p0 = cvt_tf32(p0); p1 = cvt_tf32(p1);
                p2 = cvt_tf32(p2); p3 = cvt_tf32(p3);
                l0 += p0 + p1;
                l1 += p2 + p3;
                S[nt][0] = p0; S[nt][1] = p1; S[nt][2] = p2; S[nt][3] = p3;
            }

            // ---- P: D-frag -> A-frag permutation (in-warp) ----
            uint32_t pf[8][4];
            const int base = lane & ~3;
            const int s0 = base + (qd >> 1);
            const int s2 = s0 + 2;
            const bool odd = (qd & 1);
            #pragma unroll
            for (int nt = 0; nt < 8; nt++) {
                float x0 = __shfl_sync(0xffffffffu, S[nt][0], s0);
                float x1 = __shfl_sync(0xffffffffu, S[nt][1], s0);
                float y0 = __shfl_sync(0xffffffffu, S[nt][2], s0);
                float y1 = __shfl_sync(0xffffffffu, S[nt][3], s0);
                float x2 = __shfl_sync(0xffffffffu, S[nt][0], s2);
                float x3 = __shfl_sync(0xffffffffu, S[nt][1], s2);
                float y2 = __shfl_sync(0xffffffffu, S[nt][2], s2);
                float y3 = __shfl_sync(0xffffffffu, S[nt][3], s2);
                pf[nt][0] = __float_as_uint(odd ? x1 : x0);
                pf[nt][1] = __float_as_uint(odd ? y1 : y0);
                pf[nt][2] = __float_as_uint(odd ? x3 : x2);
                pf[nt][3] = __float_as_uint(odd ? y3 : y2);
            }

            // ---- O += P @ V (VT is dim-major) ----
            #pragma unroll
            for (int k = 0; k < 8; k++) {
                uint32_t bf[8][2];
                #pragma unroll
                for (int g = 0; g < 4; g++) {
                    uint32_t addr = vsm + (16 * g + lrow) * KSTRIDE_B + lofs + k * 32;
                    ldm4(bf[2*g][0], bf[2*g][1], bf[2*g+1][0], bf[2*g+1][1], addr);
                }
                #pragma unroll
                for (int nt = 0; nt < 8; nt++) mma8(O[nt], pf[k], bf[nt]);
            }
            step++;
        }

        // ---- epilogue: reduce l over quad, normalize, store ----
        l0 += __shfl_xor_sync(0xffffffffu, l0, 1);
        l0 += __shfl_xor_sync(0xffffffffu, l0, 2);
        l1 += __shfl_xor_sync(0xffffffffu, l1, 1);
        l1 += __shfl_xor_sync(0xffffffffu, l1, 2);
        const float inv0 = 1.f / l0, inv1 = 1.f / l1;

        float* og = out + ((size_t)b * T + qt * 64 + 16 * wid) * HS;
        #pragma unroll
        for (int nt = 0; nt < 8; nt++) {
            int c0 = 8 * nt + 2 * qd;
            float2 lo = make_float2(O[nt][0] * inv0, O[nt][1] * inv0);
            float2 hi = make_float2(O[nt][2] * inv1, O[nt][3] * inv1);
            *reinterpret_cast<float2*>(og + (gid    ) * 64 + c0) = lo;
            *reinterpret_cast<float2*>(og + (gid + 8) * 64 + c0) = hi;
        }
    }
}

// ---------------------------------------------------------------------------
extern "C" void kernel_launch(void* const* d_in, const int* in_sizes, int n_in,
                              void* d_out, int out_size)
{
    const float* x  = (const float*)d_in[0];
    const float* Wk = (const float*)d_in[1];
    const float* Wq = (const float*)d_in[2];
    const float* Wv = (const float*)d_in[3];
    float* out = (float*)d_out;

    cudaFuncSetAttribute(flash_mma,
                         cudaFuncAttributeMaxDynamicSharedMemorySize, FLASH_SMEM);

    proj_fused<<<(B * T) / 64, 256>>>(x, Wk, Wq, Wv);
    flash_mma<<<dim3(32, B), 128, FLASH_SMEM>>>(out);
}